// round 13
// baseline (speedup 1.0000x reference)
#include <cuda_runtime.h>
#include <cuda_bf16.h>
#include <cstdint>

#define C 8
#define G 2048      // gen rows per class
#define T 4096      // targets per class (gen + pos)
#define D 64
#define NTOT (C*G)  // 16384

// ---------------- scratch (device globals: allocation-free contract) -------
__device__ float g_K[(size_t)C * G * T];   // 256 MB kernel matrix
__device__ float g_sqg[NTOT];
__device__ float g_sqp[NTOT];
__device__ float g_rowsum[C * G];
__device__ float g_rr[C * G];              // rsqrt(row sums)
__device__ float g_colsum[C * T];
__device__ float g_rc[C * T];              // rsqrt(col sums)
__device__ float g_acc[2];                 // loss sum, drift sum
// split-bf16 copies (packed bf16x2, 32 words per row of 64 dims)
__device__ uint32_t g_gh[(size_t)NTOT * 32];
__device__ uint32_t g_gl[(size_t)NTOT * 32];
__device__ uint32_t g_ph[(size_t)NTOT * 32];
__device__ uint32_t g_pl[(size_t)NTOT * 32];

// ---------------- helpers ---------------------------------------------------
__device__ __forceinline__ uint32_t smem_u32(const void* p) {
    uint32_t a;
    asm("{ .reg .u64 t; cvta.to.shared.u64 t, %1; cvt.u32.u64 %0, t; }"
        : "=r"(a) : "l"(p));
    return a;
}
__device__ __forceinline__ uint32_t swz(uint32_t off) {   // SW128 on 128B rows
    return off ^ ((off >> 3) & 0x70);
}
__device__ __forceinline__ void ldsm_x4(uint32_t* r, uint32_t addr) {
    asm volatile("ldmatrix.sync.aligned.m8n8.x4.shared.b16 {%0,%1,%2,%3}, [%4];"
                 : "=r"(r[0]), "=r"(r[1]), "=r"(r[2]), "=r"(r[3]) : "r"(addr));
}
__device__ __forceinline__ void mma16816(float* c, const uint32_t* a,
                                         const uint32_t* b) {
    asm volatile(
        "mma.sync.aligned.m16n8k16.row.col.f32.bf16.bf16.f32 "
        "{%0,%1,%2,%3}, {%4,%5,%6,%7}, {%8,%9}, {%0,%1,%2,%3};"
        : "+f"(c[0]), "+f"(c[1]), "+f"(c[2]), "+f"(c[3])
        : "r"(a[0]), "r"(a[1]), "r"(a[2]), "r"(a[3]), "r"(b[0]), "r"(b[1]));
}
__device__ __forceinline__ float kval(float q, float ts, float dot,
                                      int gj, int gi) {
    float d2 = q + ts - 2.f * dot;
    float dist = sqrtf(fmaxf(d2, 0.f)) * 0.125f;   // /sqrt(64)
    return (gj == gi) ? 0.f : __expf(-20.f * dist);
}

// ---------------- init ------------------------------------------------------
__global__ void k_init() {
    int i = blockIdx.x * 256 + threadIdx.x;
    if (i < C * T)  g_colsum[i] = 0.f;
    if (i < C * G)  g_rowsum[i] = 0.f;
    if (i < 2)      g_acc[i]    = 0.f;
}

// ---------------- prep: split fp32 -> bf16 hi/lo (packed x2) ----------------
__global__ void k_prep(const float* __restrict__ gen, const float* __restrict__ pos) {
    int i = blockIdx.x * 256 + threadIdx.x;          // pair index
    if (i >= 2 * NTOT * 32) return;
    bool isg = i < NTOT * 32;
    int k = isg ? i : i - NTOT * 32;
    float2 v = ((const float2*)(isg ? gen : pos))[k];
    __nv_bfloat16 h0 = __float2bfloat16(v.x);
    __nv_bfloat16 h1 = __float2bfloat16(v.y);
    __nv_bfloat16 l0 = __float2bfloat16(v.x - __bfloat162float(h0));
    __nv_bfloat16 l1 = __float2bfloat16(v.y - __bfloat162float(h1));
    uint32_t hp = ((uint32_t)__bfloat16_as_ushort(h1) << 16) | __bfloat16_as_ushort(h0);
    uint32_t lp = ((uint32_t)__bfloat16_as_ushort(l1) << 16) | __bfloat16_as_ushort(l0);
    if (isg) { g_gh[k] = hp; g_gl[k] = lp; }
    else     { g_ph[k] = hp; g_pl[k] = lp; }
}

// ---------------- squared norms --------------------------------------------
__global__ void k_sqnorm(const float* __restrict__ gen, const float* __restrict__ pos) {
    int r = blockIdx.x * 256 + threadIdx.x;
    if (r >= 2 * NTOT) return;
    const float* src = (r < NTOT) ? gen + (size_t)r * D : pos + (size_t)(r - NTOT) * D;
    const float4* p = (const float4*)src;
    float s = 0.f;
#pragma unroll
    for (int q = 0; q < 16; q++) {
        float4 v = p[q];
        s += v.x * v.x + v.y * v.y + v.z * v.z + v.w * v.w;
    }
    if (r < NTOT) g_sqg[r] = s; else g_sqp[r - NTOT] = s;
}

// ---------------- pass 1 (HMMA): K = exp(-20*dist), fused row+col sums ------
// 256 thr, CTA tile 128x128, warp grid 2m x 4n, warp tile 64x32.
// K=64 bf16 per split, splits: hh + hl + lh.
// dyn smem: qs[128] | tss[128] | A_hi 16K | A_lo 16K | B_hi 16K | B_lo 16K
#define P1_SMEM (1024 + 4 * 16384)
__global__ void __launch_bounds__(256, 2) k_pass1_tc() {
    extern __shared__ __align__(16) char smem[];
    float* qs  = (float*)smem;           // 128 floats
    float* tss = (float*)(smem + 512);   // 128 floats
    const int A_HI = 1024, A_LO = A_HI + 16384, B_HI = A_LO + 16384, B_LO = B_HI + 16384;

    int cls = blockIdx.z;
    int i0 = blockIdx.y * 128;
    int j0 = blockIdx.x * 128;
    int t = threadIdx.x;

    if (t < 128) {
        qs[t] = g_sqg[cls * G + i0 + t];
    } else {
        int j = t - 128;
        int jg = j0 + j;
        tss[j] = (jg < G) ? g_sqg[cls * G + jg] : g_sqp[cls * G + jg - G];
    }
    // A tile: 128 gen rows x 32 words (hi + lo)
    {
        const uint32_t* gh = g_gh + (size_t)(cls * G + i0) * 32;
        const uint32_t* gl = g_gl + (size_t)(cls * G + i0) * 32;
#pragma unroll
        for (int l = 0; l < 16; l++) {
            int idx = t + 256 * l;
            int row = idx >> 5, pr = idx & 31;
            uint32_t off = swz(row * 128 + pr * 4);
            *(uint32_t*)(smem + A_HI + off) = gh[idx];
            *(uint32_t*)(smem + A_LO + off) = gl[idx];
        }
    }
    // B tile: 128 target rows x 32 words (hi + lo)
#pragma unroll
    for (int l = 0; l < 16; l++) {
        int idx = t + 256 * l;
        int row = idx >> 5, pr = idx & 31;
        int jg = j0 + row;
        size_t e;
        uint32_t hp, lp;
        if (jg < G) { e = (size_t)(cls * G + jg) * 32 + pr;     hp = g_gh[e]; lp = g_gl[e]; }
        else        { e = (size_t)(cls * G + jg - G) * 32 + pr; hp = g_ph[e]; lp = g_pl[e]; }
        uint32_t off = swz(row * 128 + pr * 4);
        *(uint32_t*)(smem + B_HI + off) = hp;
        *(uint32_t*)(smem + B_LO + off) = lp;
    }
    __syncthreads();

    uint32_t sb = smem_u32(smem);
    int w = t >> 5, lane = t & 31;
    int m0w = (w >> 2) * 64;
    int n0w = (w & 3) * 32;

    // ldmatrix lane address bases
    int rowA0 = m0w + (lane & 15);
    uint32_t cbA = ((uint32_t)lane >> 4) * 16;
    uint32_t xorA = (uint32_t)(rowA0 & 7) * 16;
    uint32_t baseA[4];
#pragma unroll
    for (int f = 0; f < 4; f++) baseA[f] = (uint32_t)(rowA0 + f * 16) * 128 + cbA;

    int rowB = n0w + (lane & 7) + ((lane >> 4) & 1) * 8;
    uint32_t cbB = (((uint32_t)lane >> 3) & 1) * 16;
    uint32_t xorB = (uint32_t)(rowB & 7) * 16;
    uint32_t baseB[2];
    baseB[0] = (uint32_t)rowB * 128 + cbB;
    baseB[1] = baseB[0] + 16 * 128;

    float acc[4][4][4] = {};
    uint32_t bh[2][4], bl[2][4], a[4];
#pragma unroll
    for (int ks = 0; ks < 4; ks++) {
        uint32_t kof = ks * 32;
        ldsm_x4(bh[0], sb + B_HI + ((baseB[0] + kof) ^ xorB));
        ldsm_x4(bh[1], sb + B_HI + ((baseB[1] + kof) ^ xorB));
        ldsm_x4(bl[0], sb + B_LO + ((baseB[0] + kof) ^ xorB));
        ldsm_x4(bl[1], sb + B_LO + ((baseB[1] + kof) ^ xorB));
#pragma unroll
        for (int f = 0; f < 4; f++) {
            ldsm_x4(a, sb + A_HI + ((baseA[f] + kof) ^ xorA));
#pragma unroll
            for (int g = 0; g < 4; g++)          // hi * hi
                mma16816(acc[f][g], a, &bh[g >> 1][(g & 1) * 2]);
#pragma unroll
            for (int g = 0; g < 4; g++)          // hi * lo
                mma16816(acc[f][g], a, &bl[g >> 1][(g & 1) * 2]);
            ldsm_x4(a, sb + A_LO + ((baseA[f] + kof) ^ xorA));
#pragma unroll
            for (int g = 0; g < 4; g++)          // lo * hi
                mma16816(acc[f][g], a, &bh[g >> 1][(g & 1) * 2]);
        }
    }

    // ---- epilogue: dist -> exp -> K, fused row & col sums ----
    int qr = lane >> 2;
    int qc = (lane & 3) * 2;
    float cs0[4] = {0.f, 0.f, 0.f, 0.f};
    float cs1[4] = {0.f, 0.f, 0.f, 0.f};
#pragma unroll
    for (int f = 0; f < 4; f++) {
        int r0 = m0w + f * 16 + qr;
        int r1 = r0 + 8;
        float q0 = qs[r0], q1 = qs[r1];
        int gi0 = i0 + r0, gi1 = i0 + r1;
        float* K0 = g_K + ((size_t)cls * G + gi0) * T + j0;
        float* K1 = g_K + ((size_t)cls * G + gi1) * T + j0;
        float rs0 = 0.f, rs1 = 0.f;
#pragma unroll
        for (int g = 0; g < 4; g++) {
            int c0 = n0w + g * 8 + qc;
            float t0 = tss[c0], t1 = tss[c0 + 1];
            float v00 = kval(q0, t0, acc[f][g][0], j0 + c0,     gi0);
            float v01 = kval(q0, t1, acc[f][g][1], j0 + c0 + 1, gi0);
            float v10 = kval(q1, t0, acc[f][g][2], j0 + c0,     gi1);
            float v11 = kval(q1, t1, acc[f][g][3], j0 + c0 + 1, gi1);
            rs0 += v00 + v01;  rs1 += v10 + v11;
            cs0[g] += v00 + v10;  cs1[g] += v01 + v11;
            *(float2*)(K0 + c0) = make_float2(v00, v01);
            *(float2*)(K1 + c0) = make_float2(v10, v11);
        }
        rs0 += __shfl_xor_sync(0xffffffffu, rs0, 1);
        rs0 += __shfl_xor_sync(0xffffffffu, rs0, 2);
        rs1 += __shfl_xor_sync(0xffffffffu, rs1, 1);
        rs1 += __shfl_xor_sync(0xffffffffu, rs1, 2);
        if ((lane & 3) == 0) {
            atomicAdd(&g_rowsum[cls * G + gi0], rs0);
            atomicAdd(&g_rowsum[cls * G + gi1], rs1);
        }
    }
#pragma unroll
    for (int g = 0; g < 4; g++) {
        cs0[g] += __shfl_xor_sync(0xffffffffu, cs0[g], 4);
        cs0[g] += __shfl_xor_sync(0xffffffffu, cs0[g], 8);
        cs0[g] += __shfl_xor_sync(0xffffffffu, cs0[g], 16);
        cs1[g] += __shfl_xor_sync(0xffffffffu, cs1[g], 4);
        cs1[g] += __shfl_xor_sync(0xffffffffu, cs1[g], 8);
        cs1[g] += __shfl_xor_sync(0xffffffffu, cs1[g], 16);
        if (lane < 4) {
            int c = j0 + n0w + g * 8 + qc;
            atomicAdd(&g_colsum[cls * T + c],     cs0[g]);
            atomicAdd(&g_colsum[cls * T + c + 1], cs1[g]);
        }
    }
}

// ---------------- rr / rc ----------------------------------------------------
__global__ void k_rc() {
    int i = blockIdx.x * 256 + threadIdx.x;
    if (i < C * T) g_rc[i] = rsqrtf(g_colsum[i]);
    if (i < C * G) g_rr[i] = rsqrtf(g_rowsum[i]);
}

// ---------------- pass 2: weighted GEMM + V + reductions --------------------
__global__ void __launch_bounds__(256) k_pass2(const float* __restrict__ gen,
                                               const float* __restrict__ pos) {
    int cls = blockIdx.y;
    int i0 = blockIdx.x * 32;
    const float* genC = gen + (size_t)cls * G * D;
    const float* posC = pos + (size_t)cls * G * D;
    const float* Kcls = g_K + (size_t)cls * G * T;

    __shared__ __align__(16) float ws_s[64][34];   // [j][row]
    __shared__ __align__(16) float ts_s[64][64];   // [j][d]
    __shared__ float rrs[32];
    __shared__ float sgS[32], spS[32];
    __shared__ float blk[2][16];

    int t = threadIdx.x;
    int tx = t & 15, ty = t >> 4;
    if (t < 32) rrs[t] = g_rr[cls * G + i0 + t];

    float accN[2][4] = {}, accP[2][4] = {};
    float sN[2] = {0.f, 0.f}, sP[2] = {0.f, 0.f};

    for (int jt = 0; jt < 64; jt++) {
        int jg0 = jt * 64;
        __syncthreads();
#pragma unroll
        for (int l = 0; l < 4; l++) {
            int idx4 = t + 256 * l;
            int jr = idx4 >> 4;
            int d4 = (idx4 & 15) << 2;
            int jg = jg0 + jr;
            const float* src = (jg < G) ? (genC + (size_t)jg * D)
                                        : (posC + (size_t)(jg - G) * D);
            *(float4*)&ts_s[jr][d4] = *(const float4*)(src + d4);
        }
        int jb = cls * T + jg0 + tx * 4;
        float rc0 = g_rc[jb + 0], rc1 = g_rc[jb + 1];
        float rc2 = g_rc[jb + 2], rc3 = g_rc[jb + 3];
        float sl0 = 0.f, sl1 = 0.f;
#pragma unroll
        for (int r = 0; r < 2; r++) {
            int row = ty * 2 + r;
            float rrv = rrs[row];
            float4 kv = *(const float4*)(Kcls + (size_t)(i0 + row) * T + jg0 + tx * 4);
            float w0 = fminf(rrv * rc0, 1e6f) * kv.x;
            float w1 = fminf(rrv * rc1, 1e6f) * kv.y;
            float w2 = fminf(rrv * rc2, 1e6f) * kv.z;
            float w3 = fminf(rrv * rc3, 1e6f) * kv.w;
            ws_s[tx * 4 + 0][row] = w0; ws_s[tx * 4 + 1][row] = w1;
            ws_s[tx * 4 + 2][row] = w2; ws_s[tx * 4 + 3][row] = w3;
            float ss = (w0 + w1) + (w2 + w3);
            if (r == 0) sl0 = ss; else sl1 = ss;
        }
        __syncthreads();

        if (jg0 < G) {
            sN[0] += sl0; sN[1] += sl1;
#pragma unroll 16
            for (int j = 0; j < 64; j++) {
                float2 a = *(const float2*)&ws_s[j][ty * 2];
                float4 b = *(const float4*)&ts_s[j][tx * 4];
                accN[0][0] += a.x * b.x; accN[0][1] += a.x * b.y;
                accN[0][2] += a.x * b.z; accN[0][3] += a.x * b.w;
                accN[1][0] += a.y * b.x; accN[1][1] += a.y * b.y;
                accN[1][2] += a.y * b.z; accN[1][3] += a.y * b.w;
            }
        } else {
            sP[0] += sl0; sP[1] += sl1;
#pragma unroll 16
            for (int j = 0; j < 64; j++) {
                float2 a = *(const float2*)&ws_s[j][ty * 2];
                float4 b = *(const float4*)&ts_s[j][tx * 4];
                accP[0][0] += a.x * b.x; accP[0][1] += a.x * b.y;
                accP[0][2] += a.x * b.z; accP[0][3] += a.x * b.w;
                accP[1][0] += a.y * b.x; accP[1][1] += a.y * b.y;
                accP[1][2] += a.y * b.z; accP[1][3] += a.y * b.w;
            }
        }
    }

#pragma unroll
    for (int off = 8; off > 0; off >>= 1) {
        sN[0] += __shfl_down_sync(0xffffffffu, sN[0], off, 16);
        sN[1] += __shfl_down_sync(0xffffffffu, sN[1], off, 16);
        sP[0] += __shfl_down_sync(0xffffffffu, sP[0], off, 16);
        sP[1] += __shfl_down_sync(0xffffffffu, sP[1], off, 16);
    }
    if (tx == 0) {
        sgS[ty * 2 + 0] = sN[0]; sgS[ty * 2 + 1] = sN[1];
        spS[ty * 2 + 0] = sP[0]; spS[ty * 2 + 1] = sP[1];
    }
    __syncthreads();

    float lossp = 0.f;
    float rv2[2] = {0.f, 0.f};
#pragma unroll
    for (int r = 0; r < 2; r++) {
        float sg = sgS[ty * 2 + r], sp = spS[ty * 2 + r];
#pragma unroll
        for (int q = 0; q < 4; q++) {
            float v = sg * accP[r][q] - sp * accN[r][q];
            lossp += v * v;
            rv2[r] += v * v;
        }
    }
#pragma unroll
    for (int off = 8; off > 0; off >>= 1) {
        lossp  += __shfl_down_sync(0xffffffffu, lossp,  off, 16);
        rv2[0] += __shfl_down_sync(0xffffffffu, rv2[0], off, 16);
        rv2[1] += __shfl_down_sync(0xffffffffu, rv2[1], off, 16);
    }
    if (tx == 0) {
        blk[0][ty] = lossp;
        blk[1][ty] = sqrtf(rv2[0]) + sqrtf(rv2[1]);
    }
    __syncthreads();
    if (t == 0) {
        float L = 0.f, Dr = 0.f;
#pragma unroll
        for (int q = 0; q < 16; q++) { L += blk[0][q]; Dr += blk[1][q]; }
        atomicAdd(&g_acc[0], L);
        atomicAdd(&g_acc[1], Dr);
    }
}

// ---------------- finalize ---------------------------------------------------
__global__ void k_final(float* __restrict__ out, int out_size) {
    int i = threadIdx.x;
    if (i >= out_size) return;
    float v = 0.f;
    if (i == 0) v = g_acc[0] / (float)((size_t)NTOT * D);
    else if (i == 1) v = g_acc[1] / (float)NTOT;
    out[i] = v;
}

// ---------------- launch -----------------------------------------------------
extern "C" void kernel_launch(void* const* d_in, const int* in_sizes, int n_in,
                              void* d_out, int out_size) {
    (void)in_sizes; (void)n_in;
    const float* gen = (const float*)d_in[0];   // generated [16384,64]
    const float* pos = (const float*)d_in[2];   // positive  [16384,64]
    float* out = (float*)d_out;

    cudaFuncSetAttribute(k_pass1_tc, cudaFuncAttributeMaxDynamicSharedMemorySize,
                         P1_SMEM);

    k_init<<<(C * T + 255) / 256, 256>>>();
    k_prep<<<(2 * NTOT * 32 + 255) / 256, 256>>>(gen, pos);
    k_sqnorm<<<(2 * NTOT + 255) / 256, 256>>>(gen, pos);
    k_pass1_tc<<<dim3(T / 128, G / 128, C), 256, P1_SMEM>>>();
    k_rc<<<(C * T + 255) / 256, 256>>>();
    k_pass2<<<dim3(G / 32, C), 256>>>(gen, pos);
    k_final<<<1, 32>>>(out, out_size);
}

// round 14
// speedup vs baseline: 1.0490x; 1.0490x over previous
#include <cuda_runtime.h>
#include <cuda_bf16.h>
#include <cstdint>

#define C 8
#define G 2048      // gen rows per class
#define T 4096      // targets per class (gen + pos)
#define D 64
#define NTOT (C*G)  // 16384

// ---------------- scratch (device globals: allocation-free contract) -------
__device__ float g_K[(size_t)C * G * T];   // 256 MB kernel matrix
__device__ float g_sqg[NTOT];
__device__ float g_sqp[NTOT];
__device__ float g_rowsum[C * G];
__device__ float g_rr[C * G];              // rsqrt(row sums)
__device__ float g_colsum[C * T];
__device__ float g_rc[C * T];              // rsqrt(col sums)
__device__ float g_acc[2];                 // loss sum, drift sum
// split-bf16 copies (packed bf16x2, 32 words per row of 64 dims)
__device__ uint32_t g_gh[(size_t)NTOT * 32];
__device__ uint32_t g_gl[(size_t)NTOT * 32];
__device__ uint32_t g_ph[(size_t)NTOT * 32];
__device__ uint32_t g_pl[(size_t)NTOT * 32];

// ---------------- helpers ---------------------------------------------------
__device__ __forceinline__ uint32_t smem_u32(const void* p) {
    uint32_t a;
    asm("{ .reg .u64 t; cvta.to.shared.u64 t, %1; cvt.u32.u64 %0, t; }"
        : "=r"(a) : "l"(p));
    return a;
}
__device__ __forceinline__ uint32_t swz(uint32_t off) {   // SW128 on 128B rows
    return off ^ ((off >> 3) & 0x70);
}
__device__ __forceinline__ void ldsm_x4(uint32_t* r, uint32_t addr) {
    asm volatile("ldmatrix.sync.aligned.m8n8.x4.shared.b16 {%0,%1,%2,%3}, [%4];"
                 : "=r"(r[0]), "=r"(r[1]), "=r"(r[2]), "=r"(r[3]) : "r"(addr));
}
__device__ __forceinline__ void mma16816(float* c, const uint32_t* a,
                                         const uint32_t* b) {
    asm volatile(
        "mma.sync.aligned.m16n8k16.row.col.f32.bf16.bf16.f32 "
        "{%0,%1,%2,%3}, {%4,%5,%6,%7}, {%8,%9}, {%0,%1,%2,%3};"
        : "+f"(c[0]), "+f"(c[1]), "+f"(c[2]), "+f"(c[3])
        : "r"(a[0]), "r"(a[1]), "r"(a[2]), "r"(a[3]), "r"(b[0]), "r"(b[1]));
}
__device__ __forceinline__ float kval(float q, float ts, float dot,
                                      int gj, int gi) {
    float d2 = q + ts - 2.f * dot;
    float dist = sqrtf(fmaxf(d2, 0.f)) * 0.125f;   // /sqrt(64)
    return (gj == gi) ? 0.f : __expf(-20.f * dist);
}

// ---------------- init ------------------------------------------------------
__global__ void k_init() {
    int i = blockIdx.x * 256 + threadIdx.x;
    if (i < C * T)  g_colsum[i] = 0.f;
    if (i < C * G)  g_rowsum[i] = 0.f;
    if (i < 2)      g_acc[i]    = 0.f;
}

// ---------------- prep: split fp32 -> bf16 hi/lo (packed x2) ----------------
__global__ void k_prep(const float* __restrict__ gen, const float* __restrict__ pos) {
    int i = blockIdx.x * 256 + threadIdx.x;          // pair index
    if (i >= 2 * NTOT * 32) return;
    bool isg = i < NTOT * 32;
    int k = isg ? i : i - NTOT * 32;
    float2 v = ((const float2*)(isg ? gen : pos))[k];
    __nv_bfloat16 h0 = __float2bfloat16(v.x);
    __nv_bfloat16 h1 = __float2bfloat16(v.y);
    __nv_bfloat16 l0 = __float2bfloat16(v.x - __bfloat162float(h0));
    __nv_bfloat16 l1 = __float2bfloat16(v.y - __bfloat162float(h1));
    uint32_t hp = ((uint32_t)__bfloat16_as_ushort(h1) << 16) | __bfloat16_as_ushort(h0);
    uint32_t lp = ((uint32_t)__bfloat16_as_ushort(l1) << 16) | __bfloat16_as_ushort(l0);
    if (isg) { g_gh[k] = hp; g_gl[k] = lp; }
    else     { g_ph[k] = hp; g_pl[k] = lp; }
}

// ---------------- squared norms --------------------------------------------
__global__ void k_sqnorm(const float* __restrict__ gen, const float* __restrict__ pos) {
    int r = blockIdx.x * 256 + threadIdx.x;
    if (r >= 2 * NTOT) return;
    const float* src = (r < NTOT) ? gen + (size_t)r * D : pos + (size_t)(r - NTOT) * D;
    const float4* p = (const float4*)src;
    float s = 0.f;
#pragma unroll
    for (int q = 0; q < 16; q++) {
        float4 v = p[q];
        s += v.x * v.x + v.y * v.y + v.z * v.z + v.w * v.w;
    }
    if (r < NTOT) g_sqg[r] = s; else g_sqp[r - NTOT] = s;
}

// ---------------- pass 1 (HMMA): K = exp(-20*dist), fused row+col sums ------
// 256 thr, CTA tile 128x128, warp grid 2m x 4n, warp tile 64x32.
// K=64 bf16 per split, splits: hh + hl + lh.
// dyn smem: qs[128] | tss[128] | A_hi 16K | A_lo 16K | B_hi 16K | B_lo 16K
#define P1_SMEM (1024 + 4 * 16384)
__global__ void __launch_bounds__(256, 2) k_pass1_tc() {
    extern __shared__ __align__(16) char smem[];
    float* qs  = (float*)smem;           // 128 floats
    float* tss = (float*)(smem + 512);   // 128 floats
    const int A_HI = 1024, A_LO = A_HI + 16384, B_HI = A_LO + 16384, B_LO = B_HI + 16384;

    int cls = blockIdx.z;
    int i0 = blockIdx.y * 128;
    int j0 = blockIdx.x * 128;
    int t = threadIdx.x;

    if (t < 128) {
        qs[t] = g_sqg[cls * G + i0 + t];
    } else {
        int j = t - 128;
        int jg = j0 + j;
        tss[j] = (jg < G) ? g_sqg[cls * G + jg] : g_sqp[cls * G + jg - G];
    }
    // A tile: 128 gen rows x 32 words (hi + lo)
    {
        const uint32_t* gh = g_gh + (size_t)(cls * G + i0) * 32;
        const uint32_t* gl = g_gl + (size_t)(cls * G + i0) * 32;
#pragma unroll
        for (int l = 0; l < 16; l++) {
            int idx = t + 256 * l;
            int row = idx >> 5, pr = idx & 31;
            uint32_t off = swz(row * 128 + pr * 4);
            *(uint32_t*)(smem + A_HI + off) = gh[idx];
            *(uint32_t*)(smem + A_LO + off) = gl[idx];
        }
    }
    // B tile: 128 target rows x 32 words (hi + lo)
#pragma unroll
    for (int l = 0; l < 16; l++) {
        int idx = t + 256 * l;
        int row = idx >> 5, pr = idx & 31;
        int jg = j0 + row;
        size_t e;
        uint32_t hp, lp;
        if (jg < G) { e = (size_t)(cls * G + jg) * 32 + pr;     hp = g_gh[e]; lp = g_gl[e]; }
        else        { e = (size_t)(cls * G + jg - G) * 32 + pr; hp = g_ph[e]; lp = g_pl[e]; }
        uint32_t off = swz(row * 128 + pr * 4);
        *(uint32_t*)(smem + B_HI + off) = hp;
        *(uint32_t*)(smem + B_LO + off) = lp;
    }
    __syncthreads();

    uint32_t sb = smem_u32(smem);
    int w = t >> 5, lane = t & 31;
    int m0w = (w >> 2) * 64;
    int n0w = (w & 3) * 32;

    // ldmatrix lane address bases
    int rowA0 = m0w + (lane & 15);
    uint32_t cbA = ((uint32_t)lane >> 4) * 16;
    uint32_t xorA = (uint32_t)(rowA0 & 7) * 16;
    uint32_t baseA[4];
#pragma unroll
    for (int f = 0; f < 4; f++) baseA[f] = (uint32_t)(rowA0 + f * 16) * 128 + cbA;

    int rowB = n0w + (lane & 7) + ((lane >> 4) & 1) * 8;
    uint32_t cbB = (((uint32_t)lane >> 3) & 1) * 16;
    uint32_t xorB = (uint32_t)(rowB & 7) * 16;
    uint32_t baseB[2];
    baseB[0] = (uint32_t)rowB * 128 + cbB;
    baseB[1] = baseB[0] + 16 * 128;

    float acc[4][4][4] = {};
    uint32_t bh[2][4], bl[2][4], a[4];
#pragma unroll
    for (int ks = 0; ks < 4; ks++) {
        uint32_t kof = ks * 32;
        ldsm_x4(bh[0], sb + B_HI + ((baseB[0] + kof) ^ xorB));
        ldsm_x4(bh[1], sb + B_HI + ((baseB[1] + kof) ^ xorB));
        ldsm_x4(bl[0], sb + B_LO + ((baseB[0] + kof) ^ xorB));
        ldsm_x4(bl[1], sb + B_LO + ((baseB[1] + kof) ^ xorB));
#pragma unroll
        for (int f = 0; f < 4; f++) {
            ldsm_x4(a, sb + A_HI + ((baseA[f] + kof) ^ xorA));
#pragma unroll
            for (int g = 0; g < 4; g++)          // hi * hi
                mma16816(acc[f][g], a, &bh[g >> 1][(g & 1) * 2]);
#pragma unroll
            for (int g = 0; g < 4; g++)          // hi * lo
                mma16816(acc[f][g], a, &bl[g >> 1][(g & 1) * 2]);
            ldsm_x4(a, sb + A_LO + ((baseA[f] + kof) ^ xorA));
#pragma unroll
            for (int g = 0; g < 4; g++)          // lo * hi
                mma16816(acc[f][g], a, &bh[g >> 1][(g & 1) * 2]);
        }
    }

    // ---- epilogue: dist -> exp -> K, fused row & col sums ----
    int qr = lane >> 2;
    int qc = (lane & 3) * 2;
    float cs0[4] = {0.f, 0.f, 0.f, 0.f};
    float cs1[4] = {0.f, 0.f, 0.f, 0.f};
#pragma unroll
    for (int f = 0; f < 4; f++) {
        int r0 = m0w + f * 16 + qr;
        int r1 = r0 + 8;
        float q0 = qs[r0], q1 = qs[r1];
        int gi0 = i0 + r0, gi1 = i0 + r1;
        float* K0 = g_K + ((size_t)cls * G + gi0) * T + j0;
        float* K1 = g_K + ((size_t)cls * G + gi1) * T + j0;
        float rs0 = 0.f, rs1 = 0.f;
#pragma unroll
        for (int g = 0; g < 4; g++) {
            int c0 = n0w + g * 8 + qc;
            float t0 = tss[c0], t1 = tss[c0 + 1];
            float v00 = kval(q0, t0, acc[f][g][0], j0 + c0,     gi0);
            float v01 = kval(q0, t1, acc[f][g][1], j0 + c0 + 1, gi0);
            float v10 = kval(q1, t0, acc[f][g][2], j0 + c0,     gi1);
            float v11 = kval(q1, t1, acc[f][g][3], j0 + c0 + 1, gi1);
            rs0 += v00 + v01;  rs1 += v10 + v11;
            cs0[g] += v00 + v10;  cs1[g] += v01 + v11;
            *(float2*)(K0 + c0) = make_float2(v00, v01);
            *(float2*)(K1 + c0) = make_float2(v10, v11);
        }
        rs0 += __shfl_xor_sync(0xffffffffu, rs0, 1);
        rs0 += __shfl_xor_sync(0xffffffffu, rs0, 2);
        rs1 += __shfl_xor_sync(0xffffffffu, rs1, 1);
        rs1 += __shfl_xor_sync(0xffffffffu, rs1, 2);
        if ((lane & 3) == 0) {
            atomicAdd(&g_rowsum[cls * G + gi0], rs0);
            atomicAdd(&g_rowsum[cls * G + gi1], rs1);
        }
    }
#pragma unroll
    for (int g = 0; g < 4; g++) {
        cs0[g] += __shfl_xor_sync(0xffffffffu, cs0[g], 4);
        cs0[g] += __shfl_xor_sync(0xffffffffu, cs0[g], 8);
        cs0[g] += __shfl_xor_sync(0xffffffffu, cs0[g], 16);
        cs1[g] += __shfl_xor_sync(0xffffffffu, cs1[g], 4);
        cs1[g] += __shfl_xor_sync(0xffffffffu, cs1[g], 8);
        cs1[g] += __shfl_xor_sync(0xffffffffu, cs1[g], 16);
        if (lane < 4) {
            int c = j0 + n0w + g * 8 + qc;
            atomicAdd(&g_colsum[cls * T + c],     cs0[g]);
            atomicAdd(&g_colsum[cls * T + c + 1], cs1[g]);
        }
    }
}

// ---------------- rr / rc ----------------------------------------------------
__global__ void k_rc() {
    int i = blockIdx.x * 256 + threadIdx.x;
    if (i < C * T) g_rc[i] = rsqrtf(g_colsum[i]);
    if (i < C * G) g_rr[i] = rsqrtf(g_rowsum[i]);
}

// ---------------- pass 2: weighted GEMM + V + reductions --------------------
__global__ void __launch_bounds__(256) k_pass2(const float* __restrict__ gen,
                                               const float* __restrict__ pos) {
    int cls = blockIdx.y;
    int i0 = blockIdx.x * 32;
    const float* genC = gen + (size_t)cls * G * D;
    const float* posC = pos + (size_t)cls * G * D;
    const float* Kcls = g_K + (size_t)cls * G * T;

    __shared__ __align__(16) float ws_s[64][34];   // [j][row]
    __shared__ __align__(16) float ts_s[64][64];   // [j][d]
    __shared__ float rrs[32];
    __shared__ float sgS[32], spS[32];
    __shared__ float blk[2][16];

    int t = threadIdx.x;
    int tx = t & 15, ty = t >> 4;
    if (t < 32) rrs[t] = g_rr[cls * G + i0 + t];

    float accN[2][4] = {}, accP[2][4] = {};
    float sN[2] = {0.f, 0.f}, sP[2] = {0.f, 0.f};

    for (int jt = 0; jt < 64; jt++) {
        int jg0 = jt * 64;
        __syncthreads();
#pragma unroll
        for (int l = 0; l < 4; l++) {
            int idx4 = t + 256 * l;
            int jr = idx4 >> 4;
            int d4 = (idx4 & 15) << 2;
            int jg = jg0 + jr;
            const float* src = (jg < G) ? (genC + (size_t)jg * D)
                                        : (posC + (size_t)(jg - G) * D);
            *(float4*)&ts_s[jr][d4] = *(const float4*)(src + d4);
        }
        int jb = cls * T + jg0 + tx * 4;
        float rc0 = g_rc[jb + 0], rc1 = g_rc[jb + 1];
        float rc2 = g_rc[jb + 2], rc3 = g_rc[jb + 3];
        float sl0 = 0.f, sl1 = 0.f;
#pragma unroll
        for (int r = 0; r < 2; r++) {
            int row = ty * 2 + r;
            float rrv = rrs[row];
            float4 kv = *(const float4*)(Kcls + (size_t)(i0 + row) * T + jg0 + tx * 4);
            float w0 = fminf(rrv * rc0, 1e6f) * kv.x;
            float w1 = fminf(rrv * rc1, 1e6f) * kv.y;
            float w2 = fminf(rrv * rc2, 1e6f) * kv.z;
            float w3 = fminf(rrv * rc3, 1e6f) * kv.w;
            ws_s[tx * 4 + 0][row] = w0; ws_s[tx * 4 + 1][row] = w1;
            ws_s[tx * 4 + 2][row] = w2; ws_s[tx * 4 + 3][row] = w3;
            float ss = (w0 + w1) + (w2 + w3);
            if (r == 0) sl0 = ss; else sl1 = ss;
        }
        __syncthreads();

        if (jg0 < G) {
            sN[0] += sl0; sN[1] += sl1;
#pragma unroll 16
            for (int j = 0; j < 64; j++) {
                float2 a = *(const float2*)&ws_s[j][ty * 2];
                float4 b = *(const float4*)&ts_s[j][tx * 4];
                accN[0][0] += a.x * b.x; accN[0][1] += a.x * b.y;
                accN[0][2] += a.x * b.z; accN[0][3] += a.x * b.w;
                accN[1][0] += a.y * b.x; accN[1][1] += a.y * b.y;
                accN[1][2] += a.y * b.z; accN[1][3] += a.y * b.w;
            }
        } else {
            sP[0] += sl0; sP[1] += sl1;
#pragma unroll 16
            for (int j = 0; j < 64; j++) {
                float2 a = *(const float2*)&ws_s[j][ty * 2];
                float4 b = *(const float4*)&ts_s[j][tx * 4];
                accP[0][0] += a.x * b.x; accP[0][1] += a.x * b.y;
                accP[0][2] += a.x * b.z; accP[0][3] += a.x * b.w;
                accP[1][0] += a.y * b.x; accP[1][1] += a.y * b.y;
                accP[1][2] += a.y * b.z; accP[1][3] += a.y * b.w;
            }
        }
    }

#pragma unroll
    for (int off = 8; off > 0; off >>= 1) {
        sN[0] += __shfl_down_sync(0xffffffffu, sN[0], off, 16);
        sN[1] += __shfl_down_sync(0xffffffffu, sN[1], off, 16);
        sP[0] += __shfl_down_sync(0xffffffffu, sP[0], off, 16);
        sP[1] += __shfl_down_sync(0xffffffffu, sP[1], off, 16);
    }
    if (tx == 0) {
        sgS[ty * 2 + 0] = sN[0]; sgS[ty * 2 + 1] = sN[1];
        spS[ty * 2 + 0] = sP[0]; spS[ty * 2 + 1] = sP[1];
    }
    __syncthreads();

    float lossp = 0.f;
    float rv2[2] = {0.f, 0.f};
#pragma unroll
    for (int r = 0; r < 2; r++) {
        float sg = sgS[ty * 2 + r], sp = spS[ty * 2 + r];
#pragma unroll
        for (int q = 0; q < 4; q++) {
            float v = sg * accP[r][q] - sp * accN[r][q];
            lossp += v * v;
            rv2[r] += v * v;
        }
    }
#pragma unroll
    for (int off = 8; off > 0; off >>= 1) {
        lossp  += __shfl_down_sync(0xffffffffu, lossp,  off, 16);
        rv2[0] += __shfl_down_sync(0xffffffffu, rv2[0], off, 16);
        rv2[1] += __shfl_down_sync(0xffffffffu, rv2[1], off, 16);
    }
    if (tx == 0) {
        blk[0][ty] = lossp;
        blk[1][ty] = sqrtf(rv2[0]) + sqrtf(rv2[1]);
    }
    __syncthreads();
    if (t == 0) {
        float L = 0.f, Dr = 0.f;
#pragma unroll
        for (int q = 0; q < 16; q++) { L += blk[0][q]; Dr += blk[1][q]; }
        atomicAdd(&g_acc[0], L);
        atomicAdd(&g_acc[1], Dr);
    }
}

// ---------------- finalize ---------------------------------------------------
__global__ void k_final(float* __restrict__ out, int out_size) {
    int i = threadIdx.x;
    if (i >= out_size) return;
    float v = 0.f;
    if (i == 0) v = g_acc[0] / (float)((size_t)NTOT * D);
    else if (i == 1) v = g_acc[1] / (float)NTOT;
    out[i] = v;
}

// ---------------- launch -----------------------------------------------------
extern "C" void kernel_launch(void* const* d_in, const int* in_sizes, int n_in,
                              void* d_out, int out_size) {
    (void)in_sizes; (void)n_in;
    const float* gen = (const float*)d_in[0];   // generated [16384,64]
    const float* pos = (const float*)d_in[2];   // positive  [16384,64]
    float* out = (float*)d_out;

    cudaFuncSetAttribute(k_pass1_tc, cudaFuncAttributeMaxDynamicSharedMemorySize,
                         P1_SMEM);

    k_init<<<(C * T + 255) / 256, 256>>>();
    k_prep<<<(2 * NTOT * 32 + 255) / 256, 256>>>(gen, pos);
    k_sqnorm<<<(2 * NTOT + 255) / 256, 256>>>(gen, pos);
    k_pass1_tc<<<dim3(T / 128, G / 128, C), 256, P1_SMEM>>>();
    k_rc<<<(C * T + 255) / 256, 256>>>();
    k_pass2<<<dim3(G / 32, C), 256>>>(gen, pos);
    k_final<<<1, 32>>>(out, out_size);
}

// round 15
// speedup vs baseline: 1.0491x; 1.0001x over previous
#include <cuda_runtime.h>
#include <cuda_bf16.h>
#include <cstdint>

#define C 8
#define G 2048      // gen rows per class
#define T 4096      // targets per class (gen + pos)
#define D 64
#define NTOT (C*G)  // 16384

// ---------------- scratch (device globals: allocation-free contract) -------
__device__ float g_K[(size_t)C * G * T];   // 256 MB kernel matrix
__device__ float g_sqg[NTOT];
__device__ float g_sqp[NTOT];
__device__ float g_rowsum[C * G];
__device__ float g_rr[C * G];              // rsqrt(row sums)
__device__ float g_colsum[C * T];
__device__ float g_rc[C * T];              // rsqrt(col sums)
__device__ float g_acc[2];                 // loss sum, drift sum
// split-bf16 copies (packed bf16x2, 32 words per row of 64 dims)
__device__ uint32_t g_gh[(size_t)NTOT * 32];
__device__ uint32_t g_gl[(size_t)NTOT * 32];
__device__ uint32_t g_ph[(size_t)NTOT * 32];
__device__ uint32_t g_pl[(size_t)NTOT * 32];

// ---------------- helpers ---------------------------------------------------
__device__ __forceinline__ uint32_t smem_u32(const void* p) {
    uint32_t a;
    asm("{ .reg .u64 t; cvta.to.shared.u64 t, %1; cvt.u32.u64 %0, t; }"
        : "=r"(a) : "l"(p));
    return a;
}
__device__ __forceinline__ uint32_t swz(uint32_t off) {   // SW128 on 128B rows
    return off ^ ((off >> 3) & 0x70);
}
__device__ __forceinline__ void ldsm_x4(uint32_t* r, uint32_t addr) {
    asm volatile("ldmatrix.sync.aligned.m8n8.x4.shared.b16 {%0,%1,%2,%3}, [%4];"
                 : "=r"(r[0]), "=r"(r[1]), "=r"(r[2]), "=r"(r[3]) : "r"(addr));
}
__device__ __forceinline__ void mma16816(float* c, const uint32_t* a,
                                         const uint32_t* b) {
    asm volatile(
        "mma.sync.aligned.m16n8k16.row.col.f32.bf16.bf16.f32 "
        "{%0,%1,%2,%3}, {%4,%5,%6,%7}, {%8,%9}, {%0,%1,%2,%3};"
        : "+f"(c[0]), "+f"(c[1]), "+f"(c[2]), "+f"(c[3])
        : "r"(a[0]), "r"(a[1]), "r"(a[2]), "r"(a[3]), "r"(b[0]), "r"(b[1]));
}
__device__ __forceinline__ float kval(float q, float ts, float dot,
                                      int gj, int gi) {
    float d2 = q + ts - 2.f * dot;
    float dist = sqrtf(fmaxf(d2, 0.f)) * 0.125f;   // /sqrt(64)
    return (gj == gi) ? 0.f : __expf(-20.f * dist);
}

// ---------------- init ------------------------------------------------------
__global__ void k_init() {
    int i = blockIdx.x * 256 + threadIdx.x;
    if (i < C * T)  g_colsum[i] = 0.f;
    if (i < C * G)  g_rowsum[i] = 0.f;
    if (i < 2)      g_acc[i]    = 0.f;
}

// ---------------- prep: split fp32 -> bf16 hi/lo (packed x2) ----------------
__global__ void k_prep(const float* __restrict__ gen, const float* __restrict__ pos) {
    int i = blockIdx.x * 256 + threadIdx.x;          // pair index
    if (i >= 2 * NTOT * 32) return;
    bool isg = i < NTOT * 32;
    int k = isg ? i : i - NTOT * 32;
    float2 v = ((const float2*)(isg ? gen : pos))[k];
    __nv_bfloat16 h0 = __float2bfloat16(v.x);
    __nv_bfloat16 h1 = __float2bfloat16(v.y);
    __nv_bfloat16 l0 = __float2bfloat16(v.x - __bfloat162float(h0));
    __nv_bfloat16 l1 = __float2bfloat16(v.y - __bfloat162float(h1));
    uint32_t hp = ((uint32_t)__bfloat16_as_ushort(h1) << 16) | __bfloat16_as_ushort(h0);
    uint32_t lp = ((uint32_t)__bfloat16_as_ushort(l1) << 16) | __bfloat16_as_ushort(l0);
    if (isg) { g_gh[k] = hp; g_gl[k] = lp; }
    else     { g_ph[k] = hp; g_pl[k] = lp; }
}

// ---------------- squared norms --------------------------------------------
__global__ void k_sqnorm(const float* __restrict__ gen, const float* __restrict__ pos) {
    int r = blockIdx.x * 256 + threadIdx.x;
    if (r >= 2 * NTOT) return;
    const float* src = (r < NTOT) ? gen + (size_t)r * D : pos + (size_t)(r - NTOT) * D;
    const float4* p = (const float4*)src;
    float s = 0.f;
#pragma unroll
    for (int q = 0; q < 16; q++) {
        float4 v = p[q];
        s += v.x * v.x + v.y * v.y + v.z * v.z + v.w * v.w;
    }
    if (r < NTOT) g_sqg[r] = s; else g_sqp[r - NTOT] = s;
}

// ---------------- pass 1 (HMMA): K = exp(-20*dist), fused row+col sums ------
// 256 thr, CTA tile 128x128, warp grid 2m x 4n, warp tile 64x32.
// K=64 bf16 per split, splits: hh + hl + lh.
// dyn smem: qs[128] | tss[128] | A_hi 16K | A_lo 16K | B_hi 16K | B_lo 16K
#define P1_SMEM (1024 + 4 * 16384)
__global__ void __launch_bounds__(256, 2) k_pass1_tc() {
    extern __shared__ __align__(16) char smem[];
    float* qs  = (float*)smem;           // 128 floats
    float* tss = (float*)(smem + 512);   // 128 floats
    const int A_HI = 1024, A_LO = A_HI + 16384, B_HI = A_LO + 16384, B_LO = B_HI + 16384;

    int cls = blockIdx.z;
    int i0 = blockIdx.y * 128;
    int j0 = blockIdx.x * 128;
    int t = threadIdx.x;

    if (t < 128) {
        qs[t] = g_sqg[cls * G + i0 + t];
    } else {
        int j = t - 128;
        int jg = j0 + j;
        tss[j] = (jg < G) ? g_sqg[cls * G + jg] : g_sqp[cls * G + jg - G];
    }
    // A tile: 128 gen rows x 32 words (hi + lo)
    {
        const uint32_t* gh = g_gh + (size_t)(cls * G + i0) * 32;
        const uint32_t* gl = g_gl + (size_t)(cls * G + i0) * 32;
#pragma unroll
        for (int l = 0; l < 16; l++) {
            int idx = t + 256 * l;
            int row = idx >> 5, pr = idx & 31;
            uint32_t off = swz(row * 128 + pr * 4);
            *(uint32_t*)(smem + A_HI + off) = gh[idx];
            *(uint32_t*)(smem + A_LO + off) = gl[idx];
        }
    }
    // B tile: 128 target rows x 32 words (hi + lo)
#pragma unroll
    for (int l = 0; l < 16; l++) {
        int idx = t + 256 * l;
        int row = idx >> 5, pr = idx & 31;
        int jg = j0 + row;
        size_t e;
        uint32_t hp, lp;
        if (jg < G) { e = (size_t)(cls * G + jg) * 32 + pr;     hp = g_gh[e]; lp = g_gl[e]; }
        else        { e = (size_t)(cls * G + jg - G) * 32 + pr; hp = g_ph[e]; lp = g_pl[e]; }
        uint32_t off = swz(row * 128 + pr * 4);
        *(uint32_t*)(smem + B_HI + off) = hp;
        *(uint32_t*)(smem + B_LO + off) = lp;
    }
    __syncthreads();

    uint32_t sb = smem_u32(smem);
    int w = t >> 5, lane = t & 31;
    int m0w = (w >> 2) * 64;
    int n0w = (w & 3) * 32;

    // ldmatrix lane address bases
    int rowA0 = m0w + (lane & 15);
    uint32_t cbA = ((uint32_t)lane >> 4) * 16;
    uint32_t xorA = (uint32_t)(rowA0 & 7) * 16;
    uint32_t baseA[4];
#pragma unroll
    for (int f = 0; f < 4; f++) baseA[f] = (uint32_t)(rowA0 + f * 16) * 128 + cbA;

    int rowB = n0w + (lane & 7) + ((lane >> 4) & 1) * 8;
    uint32_t cbB = (((uint32_t)lane >> 3) & 1) * 16;
    uint32_t xorB = (uint32_t)(rowB & 7) * 16;
    uint32_t baseB[2];
    baseB[0] = (uint32_t)rowB * 128 + cbB;
    baseB[1] = baseB[0] + 16 * 128;

    float acc[4][4][4] = {};
    uint32_t bh[2][4], bl[2][4], a[4];
#pragma unroll
    for (int ks = 0; ks < 4; ks++) {
        uint32_t kof = ks * 32;
        ldsm_x4(bh[0], sb + B_HI + ((baseB[0] + kof) ^ xorB));
        ldsm_x4(bh[1], sb + B_HI + ((baseB[1] + kof) ^ xorB));
        ldsm_x4(bl[0], sb + B_LO + ((baseB[0] + kof) ^ xorB));
        ldsm_x4(bl[1], sb + B_LO + ((baseB[1] + kof) ^ xorB));
#pragma unroll
        for (int f = 0; f < 4; f++) {
            ldsm_x4(a, sb + A_HI + ((baseA[f] + kof) ^ xorA));
#pragma unroll
            for (int g = 0; g < 4; g++)          // hi * hi
                mma16816(acc[f][g], a, &bh[g >> 1][(g & 1) * 2]);
#pragma unroll
            for (int g = 0; g < 4; g++)          // hi * lo
                mma16816(acc[f][g], a, &bl[g >> 1][(g & 1) * 2]);
            ldsm_x4(a, sb + A_LO + ((baseA[f] + kof) ^ xorA));
#pragma unroll
            for (int g = 0; g < 4; g++)          // lo * hi
                mma16816(acc[f][g], a, &bh[g >> 1][(g & 1) * 2]);
        }
    }

    // ---- epilogue: dist -> exp -> K, fused row & col sums ----
    int qr = lane >> 2;
    int qc = (lane & 3) * 2;
    float cs0[4] = {0.f, 0.f, 0.f, 0.f};
    float cs1[4] = {0.f, 0.f, 0.f, 0.f};
#pragma unroll
    for (int f = 0; f < 4; f++) {
        int r0 = m0w + f * 16 + qr;
        int r1 = r0 + 8;
        float q0 = qs[r0], q1 = qs[r1];
        int gi0 = i0 + r0, gi1 = i0 + r1;
        float* K0 = g_K + ((size_t)cls * G + gi0) * T + j0;
        float* K1 = g_K + ((size_t)cls * G + gi1) * T + j0;
        float rs0 = 0.f, rs1 = 0.f;
#pragma unroll
        for (int g = 0; g < 4; g++) {
            int c0 = n0w + g * 8 + qc;
            float t0 = tss[c0], t1 = tss[c0 + 1];
            float v00 = kval(q0, t0, acc[f][g][0], j0 + c0,     gi0);
            float v01 = kval(q0, t1, acc[f][g][1], j0 + c0 + 1, gi0);
            float v10 = kval(q1, t0, acc[f][g][2], j0 + c0,     gi1);
            float v11 = kval(q1, t1, acc[f][g][3], j0 + c0 + 1, gi1);
            rs0 += v00 + v01;  rs1 += v10 + v11;
            cs0[g] += v00 + v10;  cs1[g] += v01 + v11;
            *(float2*)(K0 + c0) = make_float2(v00, v01);
            *(float2*)(K1 + c0) = make_float2(v10, v11);
        }
        rs0 += __shfl_xor_sync(0xffffffffu, rs0, 1);
        rs0 += __shfl_xor_sync(0xffffffffu, rs0, 2);
        rs1 += __shfl_xor_sync(0xffffffffu, rs1, 1);
        rs1 += __shfl_xor_sync(0xffffffffu, rs1, 2);
        if ((lane & 3) == 0) {
            atomicAdd(&g_rowsum[cls * G + gi0], rs0);
            atomicAdd(&g_rowsum[cls * G + gi1], rs1);
        }
    }
#pragma unroll
    for (int g = 0; g < 4; g++) {
        cs0[g] += __shfl_xor_sync(0xffffffffu, cs0[g], 4);
        cs0[g] += __shfl_xor_sync(0xffffffffu, cs0[g], 8);
        cs0[g] += __shfl_xor_sync(0xffffffffu, cs0[g], 16);
        cs1[g] += __shfl_xor_sync(0xffffffffu, cs1[g], 4);
        cs1[g] += __shfl_xor_sync(0xffffffffu, cs1[g], 8);
        cs1[g] += __shfl_xor_sync(0xffffffffu, cs1[g], 16);
        if (lane < 4) {
            int c = j0 + n0w + g * 8 + qc;
            atomicAdd(&g_colsum[cls * T + c],     cs0[g]);
            atomicAdd(&g_colsum[cls * T + c + 1], cs1[g]);
        }
    }
}

// ---------------- rr / rc ----------------------------------------------------
__global__ void k_rc() {
    int i = blockIdx.x * 256 + threadIdx.x;
    if (i < C * T) g_rc[i] = rsqrtf(g_colsum[i]);
    if (i < C * G) g_rr[i] = rsqrtf(g_rowsum[i]);
}

// ---------------- pass 2: weighted GEMM + V + reductions --------------------
__global__ void __launch_bounds__(256) k_pass2(const float* __restrict__ gen,
                                               const float* __restrict__ pos) {
    int cls = blockIdx.y;
    int i0 = blockIdx.x * 32;
    const float* genC = gen + (size_t)cls * G * D;
    const float* posC = pos + (size_t)cls * G * D;
    const float* Kcls = g_K + (size_t)cls * G * T;

    __shared__ __align__(16) float ws_s[64][34];   // [j][row]
    __shared__ __align__(16) float ts_s[64][64];   // [j][d]
    __shared__ float rrs[32];
    __shared__ float sgS[32], spS[32];
    __shared__ float blk[2][16];

    int t = threadIdx.x;
    int tx = t & 15, ty = t >> 4;
    if (t < 32) rrs[t] = g_rr[cls * G + i0 + t];

    float accN[2][4] = {}, accP[2][4] = {};
    float sN[2] = {0.f, 0.f}, sP[2] = {0.f, 0.f};

    for (int jt = 0; jt < 64; jt++) {
        int jg0 = jt * 64;
        __syncthreads();
#pragma unroll
        for (int l = 0; l < 4; l++) {
            int idx4 = t + 256 * l;
            int jr = idx4 >> 4;
            int d4 = (idx4 & 15) << 2;
            int jg = jg0 + jr;
            const float* src = (jg < G) ? (genC + (size_t)jg * D)
                                        : (posC + (size_t)(jg - G) * D);
            *(float4*)&ts_s[jr][d4] = *(const float4*)(src + d4);
        }
        int jb = cls * T + jg0 + tx * 4;
        float rc0 = g_rc[jb + 0], rc1 = g_rc[jb + 1];
        float rc2 = g_rc[jb + 2], rc3 = g_rc[jb + 3];
        float sl0 = 0.f, sl1 = 0.f;
#pragma unroll
        for (int r = 0; r < 2; r++) {
            int row = ty * 2 + r;
            float rrv = rrs[row];
            float4 kv = *(const float4*)(Kcls + (size_t)(i0 + row) * T + jg0 + tx * 4);
            float w0 = fminf(rrv * rc0, 1e6f) * kv.x;
            float w1 = fminf(rrv * rc1, 1e6f) * kv.y;
            float w2 = fminf(rrv * rc2, 1e6f) * kv.z;
            float w3 = fminf(rrv * rc3, 1e6f) * kv.w;
            ws_s[tx * 4 + 0][row] = w0; ws_s[tx * 4 + 1][row] = w1;
            ws_s[tx * 4 + 2][row] = w2; ws_s[tx * 4 + 3][row] = w3;
            float ss = (w0 + w1) + (w2 + w3);
            if (r == 0) sl0 = ss; else sl1 = ss;
        }
        __syncthreads();

        if (jg0 < G) {
            sN[0] += sl0; sN[1] += sl1;
#pragma unroll 16
            for (int j = 0; j < 64; j++) {
                float2 a = *(const float2*)&ws_s[j][ty * 2];
                float4 b = *(const float4*)&ts_s[j][tx * 4];
                accN[0][0] += a.x * b.x; accN[0][1] += a.x * b.y;
                accN[0][2] += a.x * b.z; accN[0][3] += a.x * b.w;
                accN[1][0] += a.y * b.x; accN[1][1] += a.y * b.y;
                accN[1][2] += a.y * b.z; accN[1][3] += a.y * b.w;
            }
        } else {
            sP[0] += sl0; sP[1] += sl1;
#pragma unroll 16
            for (int j = 0; j < 64; j++) {
                float2 a = *(const float2*)&ws_s[j][ty * 2];
                float4 b = *(const float4*)&ts_s[j][tx * 4];
                accP[0][0] += a.x * b.x; accP[0][1] += a.x * b.y;
                accP[0][2] += a.x * b.z; accP[0][3] += a.x * b.w;
                accP[1][0] += a.y * b.x; accP[1][1] += a.y * b.y;
                accP[1][2] += a.y * b.z; accP[1][3] += a.y * b.w;
            }
        }
    }

#pragma unroll
    for (int off = 8; off > 0; off >>= 1) {
        sN[0] += __shfl_down_sync(0xffffffffu, sN[0], off, 16);
        sN[1] += __shfl_down_sync(0xffffffffu, sN[1], off, 16);
        sP[0] += __shfl_down_sync(0xffffffffu, sP[0], off, 16);
        sP[1] += __shfl_down_sync(0xffffffffu, sP[1], off, 16);
    }
    if (tx == 0) {
        sgS[ty * 2 + 0] = sN[0]; sgS[ty * 2 + 1] = sN[1];
        spS[ty * 2 + 0] = sP[0]; spS[ty * 2 + 1] = sP[1];
    }
    __syncthreads();

    float lossp = 0.f;
    float rv2[2] = {0.f, 0.f};
#pragma unroll
    for (int r = 0; r < 2; r++) {
        float sg = sgS[ty * 2 + r], sp = spS[ty * 2 + r];
#pragma unroll
        for (int q = 0; q < 4; q++) {
            float v = sg * accP[r][q] - sp * accN[r][q];
            lossp += v * v;
            rv2[r] += v * v;
        }
    }
#pragma unroll
    for (int off = 8; off > 0; off >>= 1) {
        lossp  += __shfl_down_sync(0xffffffffu, lossp,  off, 16);
        rv2[0] += __shfl_down_sync(0xffffffffu, rv2[0], off, 16);
        rv2[1] += __shfl_down_sync(0xffffffffu, rv2[1], off, 16);
    }
    if (tx == 0) {
        blk[0][ty] = lossp;
        blk[1][ty] = sqrtf(rv2[0]) + sqrtf(rv2[1]);
    }
    __syncthreads();
    if (t == 0) {
        float L = 0.f, Dr = 0.f;
#pragma unroll
        for (int q = 0; q < 16; q++) { L += blk[0][q]; Dr += blk[1][q]; }
        atomicAdd(&g_acc[0], L);
        atomicAdd(&g_acc[1], Dr);
    }
}

// ---------------- finalize ---------------------------------------------------
__global__ void k_final(float* __restrict__ out, int out_size) {
    int i = threadIdx.x;
    if (i >= out_size) return;
    float v = 0.f;
    if (i == 0) v = g_acc[0] / (float)((size_t)NTOT * D);
    else if (i == 1) v = g_acc[1] / (float)NTOT;
    out[i] = v;
}

// ---------------- launch -----------------------------------------------------
extern "C" void kernel_launch(void* const* d_in, const int* in_sizes, int n_in,
                              void* d_out, int out_size) {
    (void)in_sizes; (void)n_in;
    const float* gen = (const float*)d_in[0];   // generated [16384,64]
    const float* pos = (const float*)d_in[2];   // positive  [16384,64]
    float* out = (float*)d_out;

    cudaFuncSetAttribute(k_pass1_tc, cudaFuncAttributeMaxDynamicSharedMemorySize,
                         P1_SMEM);

    k_init<<<(C * T + 255) / 256, 256>>>();
    k_prep<<<(2 * NTOT * 32 + 255) / 256, 256>>>(gen, pos);
    k_sqnorm<<<(2 * NTOT + 255) / 256, 256>>>(gen, pos);
    k_pass1_tc<<<dim3(T / 128, G / 128, C), 256, P1_SMEM>>>();
    k_rc<<<(C * T + 255) / 256, 256>>>();
    k_pass2<<<dim3(G / 32, C), 256>>>(gen, pos);
    k_final<<<1, 32>>>(out, out_size);
}